// round 7
// baseline (speedup 1.0000x reference)
#include <cuda_runtime.h>
#include <math.h>

#define MM 48
#define LL 48
#define NN 256
#define NT 128            // threads per CTA (= per sample)
#define ZPJ 12            // max pairs per thread (single-m segments)
#define CPW (NT * ZPJ)    // checkpoint row width = 1536 floats
#define CPROWS 12         // one checkpoint per 4 sites

// smem layout (floats): ab[4608] (float2*2304) | cp[12*1536] | u[48] | part[16]
#define SM_AB   0
#define SM_CP   (2 * LL * MM)
#define SM_U    (SM_CP + CPROWS * CPW)
#define SM_PART (SM_U + LL)
#define SMEMF   (SM_PART + 16)

// Accurate f32 sincos: Cody-Waite FMA range reduction + Taylor polys.
// |x| < ~80, ~1-2 ulp, immune to --use_fast_math (no libm).
__device__ __forceinline__ void sincos_acc(float x, float* s, float* c) {
    float kf = rintf(x * 0.63661977236758134f);           // x * 2/pi
    int k = (int)kf;
    float r = fmaf(kf, -1.57079637050628662109375f, x);   // - k * fl32(pi/2)
    r = fmaf(kf, 4.37113882867379290e-8f, r);             // - k * lo correction
    float r2 = r * r;
    float ps = fmaf(r2, 2.7557314297e-06f, -1.9841270114e-04f);
    ps = fmaf(r2, ps, 8.3333337680e-03f);
    ps = fmaf(r2, ps, -1.6666667163e-01f);
    float sr = fmaf(r * r2, ps, r);
    float pc = fmaf(r2, -2.7557314297e-07f, 2.4760126951e-05f);
    pc = fmaf(r2, pc, -1.3888889225e-03f);
    pc = fmaf(r2, pc, 4.1666667908e-02f);
    float cr = fmaf(r2 * r2, pc, fmaf(r2, -0.5f, 1.0f));
    switch (k & 3) {
        case 0: *s = sr;  *c = cr;  break;
        case 1: *s = cr;  *c = -sr; break;
        case 2: *s = -sr; *c = -cr; break;
        default:*s = -cr; *c = sr;  break;
    }
}

__global__ __launch_bounds__(NT) void fused_kernel(
    const float* __restrict__ inp,      // (N,L)
    const float* __restrict__ theta,    // (L,M)
    const float* __restrict__ coef,     // (M,)
    const float* __restrict__ rand_u,   // (L,N)
    float* __restrict__ out)            // N*L bits then N probs
{
    extern __shared__ float sm[];
    float2* ab  = reinterpret_cast<float2*>(sm + SM_AB);  // [l*MM+m]
    float*  cp  = sm + SM_CP;
    float*  ush = sm + SM_U;
    float*  prt = sm + SM_PART;

    const int n = blockIdx.x, tid = threadIdx.x;
    const int lane = tid & 31, wid = tid >> 5;

    // ---- Phase A: embedding tile in smem (f32 rounding matches reference) ----
    const float PI2F = 1.57079637050628662109375f;   // fl32(pi/2)
#pragma unroll
    for (int e = tid; e < LL * MM; e += NT) {
        int l = e / MM, m = e % MM;
        float ang = inp[n * LL + l] * ((float)(m + 1) * PI2F);
        float sa, ca; sincos_acc(ang, &sa, &ca);
        float st, ct; sincos_acc(theta[e], &st, &ct);
        float cf = coef[m];
        ab[e] = make_float2(cf * (ct * ca - st * sa),   // a (p=0 comp)
                            cf * (st * ca + ct * sa));  // b (p=1 comp)
    }
    if (tid < LL) ush[tid] = rand_u[tid * NN + n];
    __syncthreads();

    // ---- segment decode: lane owns pairs (m, kst..kst+cnt-1), single m ----
    int m = 0, kst = 0, cnt = 0;
    {
        int seg = tid;
        for (int mm = 0; mm < MM; mm++) {
            int ns = (MM - mm + ZPJ - 1) / ZPJ;
            if (seg < ns) { m = mm; kst = mm + seg * ZPJ;
                            cnt = min(ZPJ, MM - kst); break; }
            seg -= ns;
        }
        // tid >= 120: cnt stays 0 (inactive lane, all weights 0)
    }

    // ---- Phase B: backward scan, store every 4th suffix row (w baked in) ----
    {
        float run[ZPJ];
#pragma unroll
        for (int j = 0; j < ZPJ; j++)
            run[j] = (j < cnt) ? ((kst + j == m) ? 1.0f : 2.0f) : 0.0f;
        for (int l = LL - 1; l >= 0; l--) {
            if ((l & 3) == 3) {                 // run == SUF(l) here
                float* row = cp + (l >> 2) * CPW + tid * ZPJ;
#pragma unroll
                for (int q = 0; q < 3; q++)
                    reinterpret_cast<float4*>(row)[q] =
                        make_float4(run[4*q], run[4*q+1], run[4*q+2], run[4*q+3]);
            }
            float2 vm = ab[l * MM + m];
#pragma unroll
            for (int j = 0; j < ZPJ; j++) {
                float2 vk = ab[l * MM + kst + j];
                run[j] *= fmaf(vm.x, vk.x, vm.y * vk.y);
            }
        }
    }
    __syncthreads();

    // ---- Phase C: zipper, 12 blocks of 4 sites. Live state per lane is only
    //      r[4][12] + P[12]; aa/bb are transient per-step (no spills). ----
    float P[ZPJ];
#pragma unroll
    for (int j = 0; j < ZPJ; j++) P[j] = (j < cnt) ? 1.0f : 0.0f;

    float denom0 = 1.0f;
    int Kexp = 0;
    unsigned long long bits = 0ull;

#pragma unroll 1
    for (int b = 0; b < CPROWS; b++) {
        const int l0 = 4 * b;
        float r0[ZPJ], r1[ZPJ], r2[ZPJ], r3[ZPJ];

        // checkpoint row -> r3 (= SUF(l0+3))
        {
            const float* crow = cp + b * CPW + tid * ZPJ;
#pragma unroll
            for (int q = 0; q < 3; q++) {
                float4 v = reinterpret_cast<const float4*>(crow)[q];
                r3[4*q] = v.x; r3[4*q+1] = v.y; r3[4*q+2] = v.z; r3[4*q+3] = v.w;
            }
        }
        // reconstruct r2, r1, r0 with on-the-fly d = aa+bb from smem
        {
            const float2* a3 = ab + (l0 + 3) * MM;
            float2 vm = a3[m];
#pragma unroll
            for (int j = 0; j < ZPJ; j++) {
                float2 vk = a3[kst + j];
                r2[j] = r3[j] * fmaf(vm.x, vk.x, vm.y * vk.y);
            }
            const float2* a2 = ab + (l0 + 2) * MM;
            vm = a2[m];
#pragma unroll
            for (int j = 0; j < ZPJ; j++) {
                float2 vk = a2[kst + j];
                r1[j] = r2[j] * fmaf(vm.x, vk.x, vm.y * vk.y);
            }
            const float2* a1 = ab + (l0 + 1) * MM;
            vm = a1[m];
#pragma unroll
            for (int j = 0; j < ZPJ; j++) {
                float2 vk = a1[kst + j];
                r0[j] = r1[j] * fmaf(vm.x, vk.x, vm.y * vk.y);
            }
        }

        // 4 sequential decision steps; aa/bb recomputed from smem per step
#pragma unroll
        for (int li = 0; li < 4; li++) {
            const int l = l0 + li;
            const float* rr = (li == 0) ? r0 : (li == 1) ? r1 : (li == 2) ? r2 : r3;
            const float2* abl = ab + l * MM;
            float2 vm = abl[m];

            float aa[ZPJ], bb[ZPJ];
            float s0 = 0.f, s1 = 0.f, t0 = 0.f, t1 = 0.f;
#pragma unroll
            for (int j = 0; j < ZPJ; j++) {
                float2 vk = abl[kst + j];
                aa[j] = vm.x * vk.x;
                bb[j] = vm.y * vk.y;
                float ps = P[j] * rr[j];
                if (j & 1) { t0 = fmaf(ps, aa[j], t0); t1 = fmaf(ps, bb[j], t1); }
                else       { s0 = fmaf(ps, aa[j], s0); s1 = fmaf(ps, bb[j], s1); }
            }
            s0 += t0; s1 += t1;
#pragma unroll
            for (int o = 16; o; o >>= 1) {
                s0 += __shfl_xor_sync(0xffffffffu, s0, o);
                s1 += __shfl_xor_sync(0xffffffffu, s1, o);
            }
            if (lane == 0) { prt[(l & 1) * 8 + wid] = s0; prt[(l & 1) * 8 + 4 + wid] = s1; }
            __syncthreads();

            const float* q = prt + (l & 1) * 8;
            float S0 = (q[0] + q[1]) + (q[2] + q[3]);
            float S1 = (q[4] + q[5]) + (q[6] + q[7]);
            float den = fabsf(S0 + S1);
            int bit = (ush[l] * den < fabsf(S1)) ? 1 : 0;   // u < |S1|/den
            if (l == 0) denom0 = den;
            int eb = (__float_as_int(den) >> 23) & 0xFF;    // exact 2^-k renorm
            int kk = eb ? (eb - 127) >> 1 : 0;
            Kexp += kk;
            float scale = __int_as_float((127 - kk) << 23);
            bits |= (unsigned long long)bit << l;
#pragma unroll
            for (int j = 0; j < ZPJ; j++)
                P[j] *= (bit ? bb[j] : aa[j]) * scale;      // lane-local update
        }
    }

    // ---- epilogue: final inner = sum w*P (true value *2^Kexp), outputs ----
    float sf = 0.0f;
#pragma unroll
    for (int j = 0; j < ZPJ; j++) {
        float w = (j < cnt) ? ((kst + j == m) ? 1.0f : 2.0f) : 0.0f;
        sf += w * P[j];
    }
#pragma unroll
    for (int o = 16; o; o >>= 1) sf += __shfl_xor_sync(0xffffffffu, sf, o);
    if (lane == 0) prt[wid] = sf;
    __syncthreads();

    if (tid < LL) out[n * LL + tid] = (float)((bits >> tid) & 1ull);
    if (tid == 0) {
        double Sf = (double)((prt[0] + prt[1]) + (prt[2] + prt[3]));
        double pmv = ldexp(fabs(Sf), Kexp) / (double)denom0;
        out[NN * LL + n] = (float)pmv;
    }
}

extern "C" void kernel_launch(void* const* d_in, const int* in_sizes, int n_in,
                              void* d_out, int out_size) {
    const float* inp    = (const float*)d_in[0];   // (N,L)
    const float* theta  = (const float*)d_in[1];   // (L,M)
    const float* coef   = (const float*)d_in[2];   // (M,)
    const float* rand_u = (const float*)d_in[3];   // (L,N)
    float* out = (float*)d_out;

    static int smem_set = 0;
    if (!smem_set) {
        cudaFuncSetAttribute(fused_kernel,
                             cudaFuncAttributeMaxDynamicSharedMemorySize,
                             SMEMF * (int)sizeof(float));
        smem_set = 1;
    }
    fused_kernel<<<NN, NT, SMEMF * sizeof(float)>>>(inp, theta, coef, rand_u, out);
}